// round 11
// baseline (speedup 1.0000x reference)
#include <cuda_runtime.h>
#include <cstdint>

#define BATCH 2
#define SEQ   2048
#define DMODEL 1024
#define NHEAD 16
#define DK    64

// Scratch (allocation-free)
__device__ float g_q[BATCH*NHEAD*SEQ*DK];
__device__ float g_k[BATCH*NHEAD*SEQ*DK];
__device__ float g_v[BATCH*NHEAD*SEQ*DK];
__device__ float g_attn[BATCH*SEQ*DMODEL];

// ---------- helpers ----------
__device__ __forceinline__ float tfr(float f) {
    unsigned u;
    asm("cvt.rna.tf32.f32 %0, %1;" : "=r"(u) : "f"(f));
    return __uint_as_float(u);
}
__device__ __forceinline__ float4 tf4(float4 v) {
    v.x = tfr(v.x); v.y = tfr(v.y); v.z = tfr(v.z); v.w = tfr(v.w);
    return v;
}
__device__ __forceinline__ void mma_tf32(float c[4],
    unsigned a0, unsigned a1, unsigned a2, unsigned a3,
    unsigned b0, unsigned b1) {
    asm volatile(
        "mma.sync.aligned.m16n8k8.row.col.f32.tf32.tf32.f32 "
        "{%0,%1,%2,%3},{%4,%5,%6,%7},{%8,%9},{%0,%1,%2,%3};"
        : "+f"(c[0]), "+f"(c[1]), "+f"(c[2]), "+f"(c[3])
        : "r"(a0), "r"(a1), "r"(a2), "r"(a3), "r"(b0), "r"(b1));
}

// ---------- projection GEMM: C = A @ W^T + bias ----------
// CTA tile 256(M) x 128(N), 8 warps of 64x64, K-chunk 32.
// Double-buffered smem, one sync per chunk (R8 pipeline).
// qkv=1: blockIdx.z selects {q,k,v}, head-split out; qkv=0: flat out.
#define PST 36
#define PA_FLOATS (256 * PST)               // 9216
#define PW_FLOATS (128 * PST)               // 4608
#define PSTAGE (PA_FLOATS + PW_FLOATS)      // 13824 floats
#define PROJ_SMEM_BYTES (2 * PSTAGE * 4)    // 110592

__global__ __launch_bounds__(256) void proj_gemm(
    const float* __restrict__ A0, const float* __restrict__ W0,
    const float* __restrict__ B0, float* __restrict__ C0,
    const float* __restrict__ A1, const float* __restrict__ W1,
    const float* __restrict__ B1, float* __restrict__ C1,
    const float* __restrict__ A2, const float* __restrict__ W2,
    const float* __restrict__ B2, float* __restrict__ C2,
    int qkv)
{
    extern __shared__ float smp[];
    const float *A = A0, *W = W0, *bias = B0;
    float* C = C0;
    if (qkv) {
        if (blockIdx.z == 1) { A = A1; W = W1; bias = B1; C = C1; }
        else if (blockIdx.z == 2) { A = A2; W = W2; bias = B2; C = C2; }
    }
    const int tid = threadIdx.x, lane = tid & 31, w = tid >> 5;
    const int g = lane >> 2, t = lane & 3;
    const int wr = w >> 1, wc = w & 1;           // warp tile: rows wr*64, cols wc*64
    const int mbase = blockIdx.y * 256, nbase = blockIdx.x * 128;
    const int arow = tid >> 3, ac4 = (tid & 7) * 4;

    float c[4][8][4];
#pragma unroll
    for (int mt = 0; mt < 4; mt++)
#pragma unroll
        for (int nt = 0; nt < 8; nt++)
#pragma unroll
            for (int i = 0; i < 4; i++) c[mt][nt][i] = 0.f;

    float4 ra[8], rw[4];
    auto ldg = [&](int kt) {
        const float* Ap = A + (size_t)(mbase + arow) * 1024 + kt * 32 + ac4;
        const float* Wp = W + (size_t)(nbase + arow) * 1024 + kt * 32 + ac4;
#pragma unroll
        for (int i = 0; i < 8; i++)
            ra[i] = *(const float4*)(Ap + (size_t)i * 32 * 1024);
#pragma unroll
        for (int i = 0; i < 4; i++)
            rw[i] = *(const float4*)(Wp + (size_t)i * 32 * 1024);
    };
    auto sts = [&](int s) {
        float* As = smp + s * PSTAGE;
        float* Ws = As + PA_FLOATS;
#pragma unroll
        for (int i = 0; i < 8; i++)
            *(float4*)(As + (arow + i * 32) * PST + ac4) = tf4(ra[i]);
#pragma unroll
        for (int i = 0; i < 4; i++)
            *(float4*)(Ws + (arow + i * 32) * PST + ac4) = tf4(rw[i]);
    };

    ldg(0); sts(0); ldg(1);
    __syncthreads();

    const int wro = wr * 64, wco = wc * 64;
    for (int kt = 0; kt < 32; kt++) {
        if (kt + 1 < 32) sts((kt + 1) & 1);
        if (kt + 2 < 32) ldg(kt + 2);
        const float* As = smp + (kt & 1) * PSTAGE;
        const float* Ws = As + PA_FLOATS;
#pragma unroll
        for (int kk = 0; kk < 4; kk++) {
            unsigned a[4][4];
#pragma unroll
            for (int mt = 0; mt < 4; mt++) {
                const float* p = As + (wro + mt * 16 + g) * PST + kk * 8 + t;
                a[mt][0] = __float_as_uint(p[0]);
                a[mt][1] = __float_as_uint(p[8 * PST]);
                a[mt][2] = __float_as_uint(p[4]);
                a[mt][3] = __float_as_uint(p[8 * PST + 4]);
            }
#pragma unroll
            for (int nt = 0; nt < 8; nt++) {
                const float* p = Ws + (wco + nt * 8 + g) * PST + kk * 8 + t;
                unsigned b0 = __float_as_uint(p[0]);
                unsigned b1 = __float_as_uint(p[4]);
#pragma unroll
                for (int mt = 0; mt < 4; mt++)
                    mma_tf32(c[mt][nt], a[mt][0], a[mt][1], a[mt][2], a[mt][3],
                             b0, b1);
            }
        }
        __syncthreads();
    }
    // epilogue
#pragma unroll
    for (int mt = 0; mt < 4; mt++)
#pragma unroll
        for (int nt = 0; nt < 8; nt++) {
            int rg0 = mbase + wro + mt * 16 + g;
            int ng0 = nbase + wco + nt * 8 + 2 * t;
#pragma unroll
            for (int ci = 0; ci < 4; ci++) {
                int mg = rg0 + ((ci >> 1) << 3);
                int ng = ng0 + (ci & 1);
                float v = c[mt][nt][ci] + __ldg(bias + ng);
                size_t idx;
                if (qkv) {
                    int b_ = mg >> 11, s = mg & 2047, h = ng >> 6, d = ng & 63;
                    idx = ((size_t)((b_ * NHEAD + h) * SEQ + s)) * DK + d;
                } else {
                    idx = (size_t)mg * DMODEL + ng;
                }
                C[idx] = v;
            }
        }
}

// ---------- flash attention ----------
// causal, warp-local softmax, shuffle P-relayout, double-buffered K/V,
// V row-major (conflict-free), one sync per KV tile.
// grid: (16 q-tiles desc, 32 b*h), 256 threads (8 warps x 16 q-rows)
#define AQ_ST 68
#define AV_ST 72
#define AKV_STAGE (64 * AQ_ST + 64 * AV_ST)          // 8960 floats
#define AOFF_S0 (128 * AQ_ST)                        // 8704
#define ATTN_SMEM_BYTES ((AOFF_S0 + 2 * AKV_STAGE) * 4)   // 106496

__global__ __launch_bounds__(256, 2) void attn_kernel()
{
    extern __shared__ float sm[];
    float* Qs = sm;

    const int qt = 15 - blockIdx.x;     // heavy tiles first
    const int bh = blockIdx.y;
    const int qbase = qt * 128;
    const float* qp = g_q + (size_t)bh * SEQ * DK;
    const float* kp = g_k + (size_t)bh * SEQ * DK;
    const float* vp = g_v + (size_t)bh * SEQ * DK;

    const int tid = threadIdx.x, lane = tid & 31, w = tid >> 5;
    const int g = lane >> 2, t = lane & 3;
    const int lrow = tid >> 4, lc4 = (tid & 15) * 4;
    const int nkt = 2 * qt + 2;

    // ---- load Q tile (tf32) ----
#pragma unroll
    for (int i = 0; i < 8; i++) {
        int f = tid + i * 256;
        int row = f >> 4, c4 = (f & 15) * 4;
        float4 v = *(const float4*)(qp + (size_t)(qbase + row) * DK + c4);
        *(float4*)(Qs + row * AQ_ST + c4) = tf4(v);
    }

    float4 kr[4], vr4[4];
    auto ldg_kv = [&](int kt) {
        const float* kpn = kp + (size_t)(kt * 64) * DK;
        const float* vpn = vp + (size_t)(kt * 64) * DK;
#pragma unroll
        for (int i = 0; i < 4; i++) {
            kr[i]  = *(const float4*)(kpn + (size_t)(lrow + i * 16) * DK + lc4);
            vr4[i] = *(const float4*)(vpn + (size_t)(lrow + i * 16) * DK + lc4);
        }
    };
    auto sts_kv = [&](int s) {
        float* Ks = sm + AOFF_S0 + s * AKV_STAGE;
        float* Vs = Ks + 64 * AQ_ST;
#pragma unroll
        for (int i = 0; i < 4; i++) {
            int row = lrow + i * 16;
            *(float4*)(Ks + row * AQ_ST + lc4) = tf4(kr[i]);
            *(float4*)(Vs + row * AV_ST + lc4) = tf4(vr4[i]);
        }
    };

    float m0 = -1e30f, m1 = -1e30f, l0 = 0.f, l1 = 0.f;
    float o[8][4];
#pragma unroll
    for (int nt = 0; nt < 8; nt++)
#pragma unroll
        for (int i = 0; i < 4; i++) o[nt][i] = 0.f;

    ldg_kv(0); sts_kv(0);
    ldg_kv(1);                  // nkt >= 2 always
    __syncthreads();

    for (int kt = 0; kt < nkt; kt++) {
        if (kt + 1 < nkt) sts_kv((kt + 1) & 1);
        if (kt + 2 < nkt) ldg_kv(kt + 2);
        const float* Ks = sm + AOFF_S0 + (kt & 1) * AKV_STAGE;
        const float* Vs = Ks + 64 * AQ_ST;
        const int kb = kt * 64;

        // ---- S = Q @ K^T ----
        float s[8][4];
#pragma unroll
        for (int nt = 0; nt < 8; nt++)
#pragma unroll
            for (int i = 0; i < 4; i++) s[nt][i] = 0.f;
#pragma unroll
        for (int kk = 0; kk < 8; kk++) {
            const float* ap = Qs + (w * 16 + g) * AQ_ST + kk * 8 + t;
            unsigned a0 = __float_as_uint(ap[0]);
            unsigned a1 = __float_as_uint(ap[8 * AQ_ST]);
            unsigned a2 = __float_as_uint(ap[4]);
            unsigned a3 = __float_as_uint(ap[8 * AQ_ST + 4]);
#pragma unroll
            for (int nt = 0; nt < 8; nt++) {
                const float* bp = Ks + (nt * 8 + g) * AQ_ST + kk * 8 + t;
                mma_tf32(s[nt], a0, a1, a2, a3,
                         __float_as_uint(bp[0]), __float_as_uint(bp[4]));
            }
        }

        // ---- scale + causal mask ----
        const bool masked = (kb + 64 > qbase);
        const int r0 = qbase + w * 16 + g, r1 = r0 + 8;
#pragma unroll
        for (int nt = 0; nt < 8; nt++) {
            int cg = kb + nt * 8 + 2 * t;
            s[nt][0] *= 0.125f; s[nt][1] *= 0.125f;
            s[nt][2] *= 0.125f; s[nt][3] *= 0.125f;
            if (masked) {
                if (cg     > r0) s[nt][0] = -1e9f;
                if (cg + 1 > r0) s[nt][1] = -1e9f;
                if (cg     > r1) s[nt][2] = -1e9f;
                if (cg + 1 > r1) s[nt][3] = -1e9f;
            }
        }

        // ---- warp-local online softmax ----
        float mc0 = -1e30f, mc1 = -1e30f;
#pragma unroll
        for (int nt = 0; nt < 8; nt++) {
            mc0 = fmaxf(mc0, fmaxf(s[nt][0], s[nt][1]));
            mc1 = fmaxf(mc1, fmaxf(s[nt][2], s[nt][3]));
        }
        mc0 = fmaxf(mc0, __shfl_xor_sync(0xffffffffu, mc0, 1));
        mc0 = fmaxf(mc0, __shfl_xor_sync(0xffffffffu, mc0, 2));
        mc1 = fmaxf(mc1, __shfl_xor_sync(0xffffffffu, mc1, 1));
        mc1 = fmaxf(mc1, __shfl_xor_sync(0xffffffffu, mc1, 2));
        float mn0 = fmaxf(m0, mc0), mn1 = fmaxf(m1, mc1);
        float al0 = __expf(m0 - mn0), al1 = __expf(m1 - mn1);
        m0 = mn0; m1 = mn1;
        l0 *= al0; l1 *= al1;
        float rs0 = 0.f, rs1 = 0.f;
#pragma unroll
        for (int nt = 0; nt < 8; nt++) {
            float p0 = __expf(s[nt][0] - mn0);
            float p1 = __expf(s[nt][1] - mn0);
            float p2 = __expf(s[nt][2] - mn1);
            float p3 = __expf(s[nt][3] - mn1);
            rs0 += p0 + p1; rs1 += p2 + p3;
            s[nt][0] = tfr(p0); s[nt][1] = tfr(p1);
            s[nt][2] = tfr(p2); s[nt][3] = tfr(p3);
            o[nt][0] *= al0; o[nt][1] *= al0;
            o[nt][2] *= al1; o[nt][3] *= al1;
        }
        rs0 += __shfl_xor_sync(0xffffffffu, rs0, 1);
        rs0 += __shfl_xor_sync(0xffffffffu, rs0, 2);
        rs1 += __shfl_xor_sync(0xffffffffu, rs1, 1);
        rs1 += __shfl_xor_sync(0xffffffffu, rs1, 2);
        l0 += rs0; l1 += rs1;

        // ---- O += P @ V (shuffle relayout; V row-major) ----
        const int L0 = g * 4 + (t >> 1);
        const int L1 = L0 + 2;
        const bool sel = t & 1;
#pragma unroll
        for (int kk = 0; kk < 8; kk++) {
            float x0 = __shfl_sync(0xffffffffu, s[kk][0], L0);
            float x1 = __shfl_sync(0xffffffffu, s[kk][1], L0);
            float x2 = __shfl_sync(0xffffffffu, s[kk][2], L0);
            float x3 = __shfl_sync(0xffffffffu, s[kk][3], L0);
            float y0 = __shfl_sync(0xffffffffu, s[kk][0], L1);
            float y1 = __shfl_sync(0xffffffffu, s[kk][1], L1);
            float y2 = __shfl_sync(0xffffffffu, s[kk][2], L1);
            float y3 = __shfl_sync(0xffffffffu, s[kk][3], L1);
            unsigned a0 = __float_as_uint(sel ? x1 : x0);
            unsigned a1 = __float_as_uint(sel ? x3 : x2);
            unsigned a2 = __float_as_uint(sel ? y1 : y0);
            unsigned a3 = __float_as_uint(sel ? y3 : y2);
            const float* brow0 = Vs + (kk * 8 + t) * AV_ST;
            const float* brow1 = Vs + (kk * 8 + t + 4) * AV_ST;
#pragma unroll
            for (int nt = 0; nt < 8; nt++) {
                mma_tf32(o[nt], a0, a1, a2, a3,
                         __float_as_uint(brow0[nt * 8 + g]),
                         __float_as_uint(brow1[nt * 8 + g]));
            }
        }
        __syncthreads();
    }

    // ---- epilogue: O/l, merge heads -> g_attn [B,S,DMODEL] ----
    const int b_ = bh >> 4, h = bh & 15;
    const float il0 = 1.f / l0, il1 = 1.f / l1;
    float* outp = g_attn + ((size_t)b_ * SEQ + qbase) * DMODEL + h * DK;
    const int rl0 = w * 16 + g;
#pragma unroll
    for (int nt = 0; nt < 8; nt++) {
        int dl = nt * 8 + 2 * t;
        outp[(size_t)rl0 * DMODEL + dl]           = o[nt][0] * il0;
        outp[(size_t)rl0 * DMODEL + dl + 1]       = o[nt][1] * il0;
        outp[(size_t)(rl0 + 8) * DMODEL + dl]     = o[nt][2] * il1;
        outp[(size_t)(rl0 + 8) * DMODEL + dl + 1] = o[nt][3] * il1;
    }
}

// ---------- launch ----------
extern "C" void kernel_launch(void* const* d_in, const int* in_sizes, int n_in,
                              void* d_out, int out_size)
{
    const float* q  = (const float*)d_in[0];
    const float* k  = (const float*)d_in[1];
    const float* v  = (const float*)d_in[2];
    const float* wq = (const float*)d_in[4];
    const float* bq = (const float*)d_in[5];
    const float* wk = (const float*)d_in[6];
    const float* bk = (const float*)d_in[7];
    const float* wv = (const float*)d_in[8];
    const float* bv = (const float*)d_in[9];
    const float* wo = (const float*)d_in[10];
    const float* bo = (const float*)d_in[11];

    float *pq, *pk, *pv, *pa;
    cudaGetSymbolAddress((void**)&pq, g_q);
    cudaGetSymbolAddress((void**)&pk, g_k);
    cudaGetSymbolAddress((void**)&pv, g_v);
    cudaGetSymbolAddress((void**)&pa, g_attn);

    cudaFuncSetAttribute(proj_gemm,
                         cudaFuncAttributeMaxDynamicSharedMemorySize,
                         PROJ_SMEM_BYTES);
    cudaFuncSetAttribute(attn_kernel,
                         cudaFuncAttributeMaxDynamicSharedMemorySize,
                         ATTN_SMEM_BYTES);

    // fused Q/K/V projections
    proj_gemm<<<dim3(8, 16, 3), 256, PROJ_SMEM_BYTES>>>(
        q, wq, bq, pq,
        k, wk, bk, pk,
        v, wv, bv, pv, 1);

    attn_kernel<<<dim3(16, 32), 256, ATTN_SMEM_BYTES>>>();

    proj_gemm<<<dim3(8, 16, 1), 256, PROJ_SMEM_BYTES>>>(
        pa, wo, bo, (float*)d_out,
        nullptr, nullptr, nullptr, nullptr,
        nullptr, nullptr, nullptr, nullptr, 0);
}

// round 12
// speedup vs baseline: 1.6766x; 1.6766x over previous
#include <cuda_runtime.h>
#include <cuda_fp16.h>
#include <cstdint>

#define BATCH 2
#define SEQ   2048
#define DMODEL 1024
#define NHEAD 16
#define DK    64

// Scratch (allocation-free)
__device__ float g_q[BATCH*NHEAD*SEQ*DK];
__device__ float g_k[BATCH*NHEAD*SEQ*DK];
__device__ float g_v[BATCH*NHEAD*SEQ*DK];
__device__ float g_attn[BATCH*SEQ*DMODEL];

// ---------- helpers ----------
__device__ __forceinline__ unsigned h2(float x, float y) {
    __half2 h = __floats2half2_rn(x, y);
    return *reinterpret_cast<unsigned*>(&h);
}
__device__ __forceinline__ uint2 cvt4(float4 v) {
    uint2 r; r.x = h2(v.x, v.y); r.y = h2(v.z, v.w); return r;
}
__device__ __forceinline__ void mma_f16(float c[4],
    unsigned a0, unsigned a1, unsigned a2, unsigned a3,
    unsigned b0, unsigned b1) {
    asm volatile(
        "mma.sync.aligned.m16n8k16.row.col.f32.f16.f16.f32 "
        "{%0,%1,%2,%3},{%4,%5,%6,%7},{%8,%9},{%0,%1,%2,%3};"
        : "+f"(c[0]), "+f"(c[1]), "+f"(c[2]), "+f"(c[3])
        : "r"(a0), "r"(a1), "r"(a2), "r"(a3), "r"(b0), "r"(b1));
}

// ---------- projection GEMM: C = A @ W^T + bias (fp16 mma) ----------
// 128x128 CTA tile, K-chunk 32, double-buffered fp16 smem, one sync per chunk.
// qkv=1: blockIdx.z selects {q,k,v}, head-split out; qkv=0: flat out.
#define PSTh 40                     // halfs per row (conflict-free frag loads)
#define PAH (128 * PSTh)            // A tile halfs
#define PSTAGEH (2 * PAH)           // A + W = 10240 halfs
#define PROJ_SMEM_BYTES (2 * PSTAGEH * 2)   // 40960

__global__ __launch_bounds__(256) void proj_gemm(
    const float* __restrict__ A0, const float* __restrict__ W0,
    const float* __restrict__ B0, float* __restrict__ C0,
    const float* __restrict__ A1, const float* __restrict__ W1,
    const float* __restrict__ B1, float* __restrict__ C1,
    const float* __restrict__ A2, const float* __restrict__ W2,
    const float* __restrict__ B2, float* __restrict__ C2,
    int qkv)
{
    extern __shared__ __half smh[];
    const float *A = A0, *W = W0, *bias = B0;
    float* C = C0;
    if (qkv) {
        if (blockIdx.z == 1) { A = A1; W = W1; bias = B1; C = C1; }
        else if (blockIdx.z == 2) { A = A2; W = W2; bias = B2; C = C2; }
    }
    const int tid = threadIdx.x, lane = tid & 31, w = tid >> 5;
    const int g = lane >> 2, t = lane & 3;
    const int wr = w >> 1, wc = w & 1;
    const int mbase = blockIdx.y * 128, nbase = blockIdx.x * 128;
    const int lrow = tid >> 3, lc4 = (tid & 7) * 4;    // + i*32 rows

    float c[2][8][4];
#pragma unroll
    for (int mt = 0; mt < 2; mt++)
#pragma unroll
        for (int nt = 0; nt < 8; nt++)
#pragma unroll
            for (int i = 0; i < 4; i++) c[mt][nt][i] = 0.f;

    float4 ra[4], rw[4];
    auto ldg = [&](int kt) {
        const float* Ap = A + (size_t)(mbase + lrow) * 1024 + kt * 32 + lc4;
        const float* Wp = W + (size_t)(nbase + lrow) * 1024 + kt * 32 + lc4;
#pragma unroll
        for (int i = 0; i < 4; i++) {
            ra[i] = *(const float4*)(Ap + (size_t)i * 32 * 1024);
            rw[i] = *(const float4*)(Wp + (size_t)i * 32 * 1024);
        }
    };
    auto sts = [&](int s) {
        __half* As = smh + s * PSTAGEH;
        __half* Ws = As + PAH;
#pragma unroll
        for (int i = 0; i < 4; i++) {
            *(uint2*)(As + (lrow + i * 32) * PSTh + lc4) = cvt4(ra[i]);
            *(uint2*)(Ws + (lrow + i * 32) * PSTh + lc4) = cvt4(rw[i]);
        }
    };

    ldg(0); sts(0); ldg(1);
    __syncthreads();

    const int wro = wr * 32, wco = wc * 64;
    for (int kt = 0; kt < 32; kt++) {
        if (kt + 1 < 32) sts((kt + 1) & 1);
        if (kt + 2 < 32) ldg(kt + 2);
        const __half* As = smh + (kt & 1) * PSTAGEH;
        const __half* Ws = As + PAH;
#pragma unroll
        for (int kk = 0; kk < 2; kk++) {
            unsigned a[2][4], b[8][2];
#pragma unroll
            for (int mt = 0; mt < 2; mt++) {
                const __half* p = As + (wro + mt * 16 + g) * PSTh + kk * 16 + 2 * t;
                a[mt][0] = *(const unsigned*)(p);
                a[mt][1] = *(const unsigned*)(p + 8 * PSTh);
                a[mt][2] = *(const unsigned*)(p + 8);
                a[mt][3] = *(const unsigned*)(p + 8 * PSTh + 8);
            }
#pragma unroll
            for (int nt = 0; nt < 8; nt++) {
                const __half* p = Ws + (wco + nt * 8 + g) * PSTh + kk * 16 + 2 * t;
                b[nt][0] = *(const unsigned*)(p);
                b[nt][1] = *(const unsigned*)(p + 8);
            }
#pragma unroll
            for (int mt = 0; mt < 2; mt++)
#pragma unroll
                for (int nt = 0; nt < 8; nt++)
                    mma_f16(c[mt][nt], a[mt][0], a[mt][1], a[mt][2], a[mt][3],
                            b[nt][0], b[nt][1]);
        }
        __syncthreads();
    }
    // epilogue (fp32 accum + bias, fp32 out)
#pragma unroll
    for (int mt = 0; mt < 2; mt++)
#pragma unroll
        for (int nt = 0; nt < 8; nt++) {
            int rg0 = mbase + wro + mt * 16 + g;
            int ng0 = nbase + wco + nt * 8 + 2 * t;
#pragma unroll
            for (int ci = 0; ci < 4; ci++) {
                int mg = rg0 + ((ci >> 1) << 3);
                int ng = ng0 + (ci & 1);
                float v = c[mt][nt][ci] + __ldg(bias + ng);
                size_t idx;
                if (qkv) {
                    int b_ = mg >> 11, s = mg & 2047, h = ng >> 6, d = ng & 63;
                    idx = ((size_t)((b_ * NHEAD + h) * SEQ + s)) * DK + d;
                } else {
                    idx = (size_t)mg * DMODEL + ng;
                }
                C[idx] = v;
            }
        }
}

// ---------- flash attention (fp16 mma, no P relayout, ldmatrix.trans V) ----------
// causal, warp-local softmax, double-buffered K/V, one sync per KV tile.
// grid: (16 q-tiles desc, 32 b*h), 256 threads (8 warps x 16 q-rows)
#define QSTh 72
#define AQH (128 * QSTh)            // 9216 halfs
#define AKH (64 * QSTh)             // 4608 halfs (K tile; V tile same)
#define ASTAGEH (2 * AKH)           // 9216 halfs per stage
#define ATTN_SMEM_BYTES ((AQH + 2 * ASTAGEH) * 2)   // 55296

__global__ __launch_bounds__(256, 2) void attn_kernel()
{
    extern __shared__ __half smh[];
    __half* Qs = smh;

    const int qt = 15 - blockIdx.x;     // heavy tiles first
    const int bh = blockIdx.y;
    const int qbase = qt * 128;
    const float* qp = g_q + (size_t)bh * SEQ * DK;
    const float* kp = g_k + (size_t)bh * SEQ * DK;
    const float* vp = g_v + (size_t)bh * SEQ * DK;

    const int tid = threadIdx.x, lane = tid & 31, w = tid >> 5;
    const int g = lane >> 2, t = lane & 3;
    const int lrow = tid >> 4, lc4 = (tid & 15) * 4;
    const int nkt = 2 * qt + 2;

    // ---- load Q tile (fp16 convert) ----
#pragma unroll
    for (int i = 0; i < 8; i++) {
        int f = tid + i * 256;
        int row = f >> 4, c4 = (f & 15) * 4;
        float4 v = *(const float4*)(qp + (size_t)(qbase + row) * DK + c4);
        *(uint2*)(Qs + row * QSTh + c4) = cvt4(v);
    }

    float4 kr[4], vr4[4];
    auto ldg_kv = [&](int kt) {
        const float* kpn = kp + (size_t)(kt * 64) * DK;
        const float* vpn = vp + (size_t)(kt * 64) * DK;
#pragma unroll
        for (int i = 0; i < 4; i++) {
            kr[i]  = *(const float4*)(kpn + (size_t)(lrow + i * 16) * DK + lc4);
            vr4[i] = *(const float4*)(vpn + (size_t)(lrow + i * 16) * DK + lc4);
        }
    };
    auto sts_kv = [&](int s) {
        __half* Ks = smh + AQH + s * ASTAGEH;
        __half* Vs = Ks + AKH;
#pragma unroll
        for (int i = 0; i < 4; i++) {
            int row = lrow + i * 16;
            *(uint2*)(Ks + row * QSTh + lc4) = cvt4(kr[i]);
            *(uint2*)(Vs + row * QSTh + lc4) = cvt4(vr4[i]);
        }
    };

    float m0 = -1e30f, m1 = -1e30f, l0 = 0.f, l1 = 0.f;
    float o[8][4];
#pragma unroll
    for (int nt = 0; nt < 8; nt++)
#pragma unroll
        for (int i = 0; i < 4; i++) o[nt][i] = 0.f;

    ldg_kv(0); sts_kv(0);
    ldg_kv(1);                  // nkt >= 2 always
    __syncthreads();

    // per-thread ldmatrix address component (row = lane&15, col-half-block)
    const unsigned vrow_off = (unsigned)(((lane & 15) * QSTh + ((lane >> 1) & 8)) * 2);

    for (int kt = 0; kt < nkt; kt++) {
        if (kt + 1 < nkt) sts_kv((kt + 1) & 1);
        if (kt + 2 < nkt) ldg_kv(kt + 2);
        const __half* Ks = smh + AQH + (kt & 1) * ASTAGEH;
        const __half* Vs = Ks + AKH;
        const int kb = kt * 64;

        // ---- S = Q @ K^T (fp16 m16n8k16) ----
        float s[8][4];
#pragma unroll
        for (int nt = 0; nt < 8; nt++)
#pragma unroll
            for (int i = 0; i < 4; i++) s[nt][i] = 0.f;
#pragma unroll
        for (int kk = 0; kk < 4; kk++) {
            const __half* ap = Qs + (w * 16 + g) * QSTh + kk * 16 + 2 * t;
            unsigned a0 = *(const unsigned*)(ap);
            unsigned a1 = *(const unsigned*)(ap + 8 * QSTh);
            unsigned a2 = *(const unsigned*)(ap + 8);
            unsigned a3 = *(const unsigned*)(ap + 8 * QSTh + 8);
#pragma unroll
            for (int nt = 0; nt < 8; nt++) {
                const __half* bp = Ks + (nt * 8 + g) * QSTh + kk * 16 + 2 * t;
                mma_f16(s[nt], a0, a1, a2, a3,
                        *(const unsigned*)(bp), *(const unsigned*)(bp + 8));
            }
        }

        // ---- scale + causal mask ----
        const bool masked = (kb + 64 > qbase);
        const int r0 = qbase + w * 16 + g, r1 = r0 + 8;
#pragma unroll
        for (int nt = 0; nt < 8; nt++) {
            int cg = kb + nt * 8 + 2 * t;
            s[nt][0] *= 0.125f; s[nt][1] *= 0.125f;
            s[nt][2] *= 0.125f; s[nt][3] *= 0.125f;
            if (masked) {
                if (cg     > r0) s[nt][0] = -1e9f;
                if (cg + 1 > r0) s[nt][1] = -1e9f;
                if (cg     > r1) s[nt][2] = -1e9f;
                if (cg + 1 > r1) s[nt][3] = -1e9f;
            }
        }

        // ---- warp-local online softmax ----
        float mc0 = -1e30f, mc1 = -1e30f;
#pragma unroll
        for (int nt = 0; nt < 8; nt++) {
            mc0 = fmaxf(mc0, fmaxf(s[nt][0], s[nt][1]));
            mc1 = fmaxf(mc1, fmaxf(s[nt][2], s[nt][3]));
        }
        mc0 = fmaxf(mc0, __shfl_xor_sync(0xffffffffu, mc0, 1));
        mc0 = fmaxf(mc0, __shfl_xor_sync(0xffffffffu, mc0, 2));
        mc1 = fmaxf(mc1, __shfl_xor_sync(0xffffffffu, mc1, 1));
        mc1 = fmaxf(mc1, __shfl_xor_sync(0xffffffffu, mc1, 2));
        float mn0 = fmaxf(m0, mc0), mn1 = fmaxf(m1, mc1);
        float al0 = __expf(m0 - mn0), al1 = __expf(m1 - mn1);
        m0 = mn0; m1 = mn1;
        l0 *= al0; l1 *= al1;
        float rs0 = 0.f, rs1 = 0.f;
#pragma unroll
        for (int nt = 0; nt < 8; nt++) {
            float p0 = __expf(s[nt][0] - mn0);
            float p1 = __expf(s[nt][1] - mn0);
            float p2 = __expf(s[nt][2] - mn1);
            float p3 = __expf(s[nt][3] - mn1);
            rs0 += p0 + p1; rs1 += p2 + p3;
            s[nt][0] = p0; s[nt][1] = p1;
            s[nt][2] = p2; s[nt][3] = p3;
            o[nt][0] *= al0; o[nt][1] *= al0;
            o[nt][2] *= al1; o[nt][3] *= al1;
        }
        rs0 += __shfl_xor_sync(0xffffffffu, rs0, 1);
        rs0 += __shfl_xor_sync(0xffffffffu, rs0, 2);
        rs1 += __shfl_xor_sync(0xffffffffu, rs1, 1);
        rs1 += __shfl_xor_sync(0xffffffffu, rs1, 2);
        l0 += rs0; l1 += rs1;

        // ---- O += P @ V ----
        // fp16 A-frags = packed pairs of adjacent S C-frags (NO shuffles).
        // V B-frags via ldmatrix.x4.trans from row-major V.
        uint32_t vb = (uint32_t)__cvta_generic_to_shared(Vs) + vrow_off;
#pragma unroll
        for (int kk = 0; kk < 4; kk++) {
            unsigned a0 = h2(s[2 * kk][0],     s[2 * kk][1]);
            unsigned a1 = h2(s[2 * kk][2],     s[2 * kk][3]);
            unsigned a2 = h2(s[2 * kk + 1][0], s[2 * kk + 1][1]);
            unsigned a3 = h2(s[2 * kk + 1][2], s[2 * kk + 1][3]);
            uint32_t rowb = vb + (uint32_t)(kk * 16 * QSTh * 2);
#pragma unroll
            for (int ntp = 0; ntp < 4; ntp++) {
                unsigned r0_, r1_, r2_, r3_;
                asm volatile(
                    "ldmatrix.sync.aligned.m8n8.x4.trans.shared.b16 "
                    "{%0,%1,%2,%3}, [%4];"
                    : "=r"(r0_), "=r"(r1_), "=r"(r2_), "=r"(r3_)
                    : "r"(rowb + (uint32_t)(ntp * 32)));
                mma_f16(o[2 * ntp],     a0, a1, a2, a3, r0_, r1_);
                mma_f16(o[2 * ntp + 1], a0, a1, a2, a3, r2_, r3_);
            }
        }
        __syncthreads();
    }

    // ---- epilogue: O/l, merge heads -> g_attn [B,S,DMODEL] ----
    const int b_ = bh >> 4, h = bh & 15;
    const float il0 = 1.f / l0, il1 = 1.f / l1;
    float* outp = g_attn + ((size_t)b_ * SEQ + qbase) * DMODEL + h * DK;
    const int rl0 = w * 16 + g;
#pragma unroll
    for (int nt = 0; nt < 8; nt++) {
        int dl = nt * 8 + 2 * t;
        outp[(size_t)rl0 * DMODEL + dl]           = o[nt][0] * il0;
        outp[(size_t)rl0 * DMODEL + dl + 1]       = o[nt][1] * il0;
        outp[(size_t)(rl0 + 8) * DMODEL + dl]     = o[nt][2] * il1;
        outp[(size_t)(rl0 + 8) * DMODEL + dl + 1] = o[nt][3] * il1;
    }
}

// ---------- launch ----------
extern "C" void kernel_launch(void* const* d_in, const int* in_sizes, int n_in,
                              void* d_out, int out_size)
{
    const float* q  = (const float*)d_in[0];
    const float* k  = (const float*)d_in[1];
    const float* v  = (const float*)d_in[2];
    const float* wq = (const float*)d_in[4];
    const float* bq = (const float*)d_in[5];
    const float* wk = (const float*)d_in[6];
    const float* bk = (const float*)d_in[7];
    const float* wv = (const float*)d_in[8];
    const float* bv = (const float*)d_in[9];
    const float* wo = (const float*)d_in[10];
    const float* bo = (const float*)d_in[11];

    float *pq, *pk, *pv, *pa;
    cudaGetSymbolAddress((void**)&pq, g_q);
    cudaGetSymbolAddress((void**)&pk, g_k);
    cudaGetSymbolAddress((void**)&pv, g_v);
    cudaGetSymbolAddress((void**)&pa, g_attn);

    cudaFuncSetAttribute(proj_gemm,
                         cudaFuncAttributeMaxDynamicSharedMemorySize,
                         PROJ_SMEM_BYTES);
    cudaFuncSetAttribute(attn_kernel,
                         cudaFuncAttributeMaxDynamicSharedMemorySize,
                         ATTN_SMEM_BYTES);

    // fused Q/K/V projections
    proj_gemm<<<dim3(8, 32, 3), 256, PROJ_SMEM_BYTES>>>(
        q, wq, bq, pq,
        k, wk, bk, pk,
        v, wv, bv, pv, 1);

    attn_kernel<<<dim3(16, 32), 256, ATTN_SMEM_BYTES>>>();

    proj_gemm<<<dim3(8, 32, 1), 256, PROJ_SMEM_BYTES>>>(
        pa, wo, bo, (float*)d_out,
        nullptr, nullptr, nullptr, nullptr,
        nullptr, nullptr, nullptr, nullptr, 0);
}

// round 13
// speedup vs baseline: 1.7037x; 1.0162x over previous
#include <cuda_runtime.h>
#include <cuda_fp16.h>
#include <cstdint>

#define BATCH 2
#define SEQ   2048
#define DMODEL 1024
#define NHEAD 16
#define DK    64

// Scratch (allocation-free)
__device__ float g_q[BATCH*NHEAD*SEQ*DK];
__device__ float g_k[BATCH*NHEAD*SEQ*DK];
__device__ float g_v[BATCH*NHEAD*SEQ*DK];
__device__ float g_attn[BATCH*SEQ*DMODEL];

// ---------- helpers ----------
__device__ __forceinline__ unsigned h2(float x, float y) {
    __half2 h = __floats2half2_rn(x, y);
    return *reinterpret_cast<unsigned*>(&h);
}
__device__ __forceinline__ uint2 cvt4(float4 v) {
    uint2 r; r.x = h2(v.x, v.y); r.y = h2(v.z, v.w); return r;
}
__device__ __forceinline__ void mma_f16(float c[4],
    unsigned a0, unsigned a1, unsigned a2, unsigned a3,
    unsigned b0, unsigned b1) {
    asm volatile(
        "mma.sync.aligned.m16n8k16.row.col.f32.f16.f16.f32 "
        "{%0,%1,%2,%3},{%4,%5,%6,%7},{%8,%9},{%0,%1,%2,%3};"
        : "+f"(c[0]), "+f"(c[1]), "+f"(c[2]), "+f"(c[3])
        : "r"(a0), "r"(a1), "r"(a2), "r"(a3), "r"(b0), "r"(b1));
}
#define LDSM_X4(r0, r1, r2, r3, addr) \
    asm volatile("ldmatrix.sync.aligned.m8n8.x4.shared.b16 {%0,%1,%2,%3}, [%4];" \
        : "=r"(r0), "=r"(r1), "=r"(r2), "=r"(r3) : "r"(addr))
#define LDSM_X4T(r0, r1, r2, r3, addr) \
    asm volatile("ldmatrix.sync.aligned.m8n8.x4.trans.shared.b16 {%0,%1,%2,%3}, [%4];" \
        : "=r"(r0), "=r"(r1), "=r"(r2), "=r"(r3) : "r"(addr))

// ---------- projection GEMM: C = A @ W^T + bias (fp16 mma + ldmatrix) ----------
// 128x128 CTA tile, K-chunk 32, double-buffered fp16 smem, one sync per chunk.
#define PSTh 40
#define PAH (128 * PSTh)
#define PSTAGEH (2 * PAH)
#define PROJ_SMEM_BYTES (2 * PSTAGEH * 2)   // 40960

__global__ __launch_bounds__(256) void proj_gemm(
    const float* __restrict__ A0, const float* __restrict__ W0,
    const float* __restrict__ B0, float* __restrict__ C0,
    const float* __restrict__ A1, const float* __restrict__ W1,
    const float* __restrict__ B1, float* __restrict__ C1,
    const float* __restrict__ A2, const float* __restrict__ W2,
    const float* __restrict__ B2, float* __restrict__ C2,
    int qkv)
{
    extern __shared__ __half smh[];
    const float *A = A0, *W = W0, *bias = B0;
    float* C = C0;
    if (qkv) {
        if (blockIdx.z == 1) { A = A1; W = W1; bias = B1; C = C1; }
        else if (blockIdx.z == 2) { A = A2; W = W2; bias = B2; C = C2; }
    }
    const int tid = threadIdx.x, lane = tid & 31, w = tid >> 5;
    const int g = lane >> 2, t = lane & 3;
    const int wr = w >> 1, wc = w & 1;
    const int mbase = blockIdx.y * 128, nbase = blockIdx.x * 128;
    const int lrow = tid >> 3, lc4 = (tid & 7) * 4;

    float c[2][8][4];
#pragma unroll
    for (int mt = 0; mt < 2; mt++)
#pragma unroll
        for (int nt = 0; nt < 8; nt++)
#pragma unroll
            for (int i = 0; i < 4; i++) c[mt][nt][i] = 0.f;

    float4 ra[4], rw[4];
    auto ldg = [&](int kt) {
        const float* Ap = A + (size_t)(mbase + lrow) * 1024 + kt * 32 + lc4;
        const float* Wp = W + (size_t)(nbase + lrow) * 1024 + kt * 32 + lc4;
#pragma unroll
        for (int i = 0; i < 4; i++) {
            ra[i] = *(const float4*)(Ap + (size_t)i * 32 * 1024);
            rw[i] = *(const float4*)(Wp + (size_t)i * 32 * 1024);
        }
    };
    auto sts = [&](int s) {
        __half* As = smh + s * PSTAGEH;
        __half* Ws = As + PAH;
#pragma unroll
        for (int i = 0; i < 4; i++) {
            *(uint2*)(As + (lrow + i * 32) * PSTh + lc4) = cvt4(ra[i]);
            *(uint2*)(Ws + (lrow + i * 32) * PSTh + lc4) = cvt4(rw[i]);
        }
    };

    ldg(0); sts(0); ldg(1);
    __syncthreads();

    const int wro = wr * 32, wco = wc * 64;
    // ldmatrix per-lane offsets (in halves)
    const int a_off = (wro + (lane & 15)) * PSTh + ((lane & 16) >> 1);
    const int b_off = (wco + (lane & 7) + ((lane & 16) >> 1)) * PSTh + (lane & 8);
    const uint32_t smbase = (uint32_t)__cvta_generic_to_shared(smh);

    for (int kt = 0; kt < 32; kt++) {
        if (kt + 1 < 32) sts((kt + 1) & 1);
        if (kt + 2 < 32) ldg(kt + 2);
        const uint32_t asb = smbase + (uint32_t)(((kt & 1) * PSTAGEH + a_off) * 2);
        const uint32_t wsb = smbase + (uint32_t)(((kt & 1) * PSTAGEH + PAH + b_off) * 2);
#pragma unroll
        for (int kk = 0; kk < 2; kk++) {
            unsigned a[2][4], b[8][2];
#pragma unroll
            for (int mt = 0; mt < 2; mt++)
                LDSM_X4(a[mt][0], a[mt][1], a[mt][2], a[mt][3],
                        asb + (uint32_t)((mt * 16 * PSTh + kk * 16) * 2));
#pragma unroll
            for (int j = 0; j < 4; j++)
                LDSM_X4(b[2 * j][0], b[2 * j][1], b[2 * j + 1][0], b[2 * j + 1][1],
                        wsb + (uint32_t)((j * 16 * PSTh + kk * 16) * 2));
#pragma unroll
            for (int mt = 0; mt < 2; mt++)
#pragma unroll
                for (int nt = 0; nt < 8; nt++)
                    mma_f16(c[mt][nt], a[mt][0], a[mt][1], a[mt][2], a[mt][3],
                            b[nt][0], b[nt][1]);
        }
        __syncthreads();
    }
    // epilogue
#pragma unroll
    for (int mt = 0; mt < 2; mt++)
#pragma unroll
        for (int nt = 0; nt < 8; nt++) {
            int rg0 = mbase + wro + mt * 16 + g;
            int ng0 = nbase + wco + nt * 8 + 2 * t;
#pragma unroll
            for (int ci = 0; ci < 4; ci++) {
                int mg = rg0 + ((ci >> 1) << 3);
                int ng = ng0 + (ci & 1);
                float v = c[mt][nt][ci] + __ldg(bias + ng);
                size_t idx;
                if (qkv) {
                    int b_ = mg >> 11, s = mg & 2047, h = ng >> 6, d = ng & 63;
                    idx = ((size_t)((b_ * NHEAD + h) * SEQ + s)) * DK + d;
                } else {
                    idx = (size_t)mg * DMODEL + ng;
                }
                C[idx] = v;
            }
        }
}

// ---------- flash attention (fp16 mma, ldmatrix everywhere) ----------
#define QSTh 72
#define AQH (128 * QSTh)
#define AKH (64 * QSTh)
#define ASTAGEH (2 * AKH)
#define ATTN_SMEM_BYTES ((AQH + 2 * ASTAGEH) * 2)   // 55296

__global__ __launch_bounds__(256, 2) void attn_kernel()
{
    extern __shared__ __half smh[];
    __half* Qs = smh;

    const int qt = 15 - blockIdx.x;
    const int bh = blockIdx.y;
    const int qbase = qt * 128;
    const float* qp = g_q + (size_t)bh * SEQ * DK;
    const float* kp = g_k + (size_t)bh * SEQ * DK;
    const float* vp = g_v + (size_t)bh * SEQ * DK;

    const int tid = threadIdx.x, lane = tid & 31, w = tid >> 5;
    const int g = lane >> 2, t = lane & 3;
    const int lrow = tid >> 4, lc4 = (tid & 15) * 4;
    const int nkt = 2 * qt + 2;

    // ---- load Q tile (fp16 convert) ----
#pragma unroll
    for (int i = 0; i < 8; i++) {
        int f = tid + i * 256;
        int row = f >> 4, c4 = (f & 15) * 4;
        float4 v = *(const float4*)(qp + (size_t)(qbase + row) * DK + c4);
        *(uint2*)(Qs + row * QSTh + c4) = cvt4(v);
    }

    float4 kr[4], vr4[4];
    auto ldg_kv = [&](int kt) {
        const float* kpn = kp + (size_t)(kt * 64) * DK;
        const float* vpn = vp + (size_t)(kt * 64) * DK;
#pragma unroll
        for (int i = 0; i < 4; i++) {
            kr[i]  = *(const float4*)(kpn + (size_t)(lrow + i * 16) * DK + lc4);
            vr4[i] = *(const float4*)(vpn + (size_t)(lrow + i * 16) * DK + lc4);
        }
    };
    auto sts_kv = [&](int s) {
        __half* Ks = smh + AQH + s * ASTAGEH;
        __half* Vs = Ks + AKH;
#pragma unroll
        for (int i = 0; i < 4; i++) {
            int row = lrow + i * 16;
            *(uint2*)(Ks + row * QSTh + lc4) = cvt4(kr[i]);
            *(uint2*)(Vs + row * QSTh + lc4) = cvt4(vr4[i]);
        }
    };

    float m0 = -1e30f, m1 = -1e30f, l0 = 0.f, l1 = 0.f;
    float o[8][4];
#pragma unroll
    for (int nt = 0; nt < 8; nt++)
#pragma unroll
        for (int i = 0; i < 4; i++) o[nt][i] = 0.f;

    ldg_kv(0); sts_kv(0);
    ldg_kv(1);
    __syncthreads();

    const uint32_t smbase = (uint32_t)__cvta_generic_to_shared(smh);
    // ldmatrix per-lane offsets (halves)
    const int q_off = (w * 16 + (lane & 15)) * QSTh + ((lane & 16) >> 1);
    const int k_off = ((lane & 7) + ((lane & 16) >> 1)) * QSTh + (lane & 8);
    const int v_off = (lane & 15) * QSTh + ((lane >> 1) & 8);
    const uint32_t qsb = smbase + (uint32_t)(q_off * 2);

    for (int kt = 0; kt < nkt; kt++) {
        if (kt + 1 < nkt) sts_kv((kt + 1) & 1);
        if (kt + 2 < nkt) ldg_kv(kt + 2);
        const uint32_t stage = (uint32_t)((AQH + (kt & 1) * ASTAGEH) * 2);
        const uint32_t ksb = smbase + stage + (uint32_t)(k_off * 2);
        const uint32_t vsb = smbase + stage + (uint32_t)((AKH + v_off) * 2);
        const int kb = kt * 64;

        // ---- S = Q @ K^T ----
        float s[8][4];
#pragma unroll
        for (int nt = 0; nt < 8; nt++)
#pragma unroll
            for (int i = 0; i < 4; i++) s[nt][i] = 0.f;
#pragma unroll
        for (int kk = 0; kk < 4; kk++) {
            unsigned a0, a1, a2, a3;
            LDSM_X4(a0, a1, a2, a3, qsb + (uint32_t)(kk * 32));
            unsigned b[8][2];
#pragma unroll
            for (int j = 0; j < 4; j++)
                LDSM_X4(b[2 * j][0], b[2 * j][1], b[2 * j + 1][0], b[2 * j + 1][1],
                        ksb + (uint32_t)((j * 16 * QSTh + kk * 16) * 2));
#pragma unroll
            for (int nt = 0; nt < 8; nt++)
                mma_f16(s[nt], a0, a1, a2, a3, b[nt][0], b[nt][1]);
        }

        // ---- scale + causal mask ----
        const bool masked = (kb + 64 > qbase);
        const int r0 = qbase + w * 16 + g, r1 = r0 + 8;
#pragma unroll
        for (int nt = 0; nt < 8; nt++) {
            int cg = kb + nt * 8 + 2 * t;
            s[nt][0] *= 0.125f; s[nt][1] *= 0.125f;
            s[nt][2] *= 0.125f; s[nt][3] *= 0.125f;
            if (masked) {
                if (cg     > r0) s[nt][0] = -1e9f;
                if (cg + 1 > r0) s[nt][1] = -1e9f;
                if (cg     > r1) s[nt][2] = -1e9f;
                if (cg + 1 > r1) s[nt][3] = -1e9f;
            }
        }

        // ---- warp-local online softmax ----
        float mc0 = -1e30f, mc1 = -1e30f;
#pragma unroll
        for (int nt = 0; nt < 8; nt++) {
            mc0 = fmaxf(mc0, fmaxf(s[nt][0], s[nt][1]));
            mc1 = fmaxf(mc1, fmaxf(s[nt][2], s[nt][3]));
        }
        mc0 = fmaxf(mc0, __shfl_xor_sync(0xffffffffu, mc0, 1));
        mc0 = fmaxf(mc0, __shfl_xor_sync(0xffffffffu, mc0, 2));
        mc1 = fmaxf(mc1, __shfl_xor_sync(0xffffffffu, mc1, 1));
        mc1 = fmaxf(mc1, __shfl_xor_sync(0xffffffffu, mc1, 2));
        float mn0 = fmaxf(m0, mc0), mn1 = fmaxf(m1, mc1);
        float al0 = __expf(m0 - mn0), al1 = __expf(m1 - mn1);
        m0 = mn0; m1 = mn1;
        l0 *= al0; l1 *= al1;
        float rs0 = 0.f, rs1 = 0.f;
#pragma unroll
        for (int nt = 0; nt < 8; nt++) {
            float p0 = __expf(s[nt][0] - mn0);
            float p1 = __expf(s[nt][1] - mn0);
            float p2 = __expf(s[nt][2] - mn1);
            float p3 = __expf(s[nt][3] - mn1);
            rs0 += p0 + p1; rs1 += p2 + p3;
            s[nt][0] = p0; s[nt][1] = p1;
            s[nt][2] = p2; s[nt][3] = p3;
            o[nt][0] *= al0; o[nt][1] *= al0;
            o[nt][2] *= al1; o[nt][3] *= al1;
        }
        rs0 += __shfl_xor_sync(0xffffffffu, rs0, 1);
        rs0 += __shfl_xor_sync(0xffffffffu, rs0, 2);
        rs1 += __shfl_xor_sync(0xffffffffu, rs1, 1);
        rs1 += __shfl_xor_sync(0xffffffffu, rs1, 2);
        l0 += rs0; l1 += rs1;

        // ---- O += P @ V (packed P frags, ldmatrix.trans V) ----
#pragma unroll
        for (int kk = 0; kk < 4; kk++) {
            unsigned a0 = h2(s[2 * kk][0],     s[2 * kk][1]);
            unsigned a1 = h2(s[2 * kk][2],     s[2 * kk][3]);
            unsigned a2 = h2(s[2 * kk + 1][0], s[2 * kk + 1][1]);
            unsigned a3 = h2(s[2 * kk + 1][2], s[2 * kk + 1][3]);
            uint32_t rowb = vsb + (uint32_t)(kk * 16 * QSTh * 2);
#pragma unroll
            for (int ntp = 0; ntp < 4; ntp++) {
                unsigned r0_, r1_, r2_, r3_;
                LDSM_X4T(r0_, r1_, r2_, r3_, rowb + (uint32_t)(ntp * 32));
                mma_f16(o[2 * ntp],     a0, a1, a2, a3, r0_, r1_);
                mma_f16(o[2 * ntp + 1], a0, a1, a2, a3, r2_, r3_);
            }
        }
        __syncthreads();
    }

    // ---- epilogue ----
    const int b_ = bh >> 4, h = bh & 15;
    const float il0 = 1.f / l0, il1 = 1.f / l1;
    float* outp = g_attn + ((size_t)b_ * SEQ + qbase) * DMODEL + h * DK;
    const int rl0 = w * 16 + g;
#pragma unroll
    for (int nt = 0; nt < 8; nt++) {
        int dl = nt * 8 + 2 * t;
        outp[(size_t)rl0 * DMODEL + dl]           = o[nt][0] * il0;
        outp[(size_t)rl0 * DMODEL + dl + 1]       = o[nt][1] * il0;
        outp[(size_t)(rl0 + 8) * DMODEL + dl]     = o[nt][2] * il1;
        outp[(size_t)(rl0 + 8) * DMODEL + dl + 1] = o[nt][3] * il1;
    }
}

// ---------- launch ----------
extern "C" void kernel_launch(void* const* d_in, const int* in_sizes, int n_in,
                              void* d_out, int out_size)
{
    const float* q  = (const float*)d_in[0];
    const float* k  = (const float*)d_in[1];
    const float* v  = (const float*)d_in[2];
    const float* wq = (const float*)d_in[4];
    const float* bq = (const float*)d_in[5];
    const float* wk = (const float*)d_in[6];
    const float* bk = (const float*)d_in[7];
    const float* wv = (const float*)d_in[8];
    const float* bv = (const float*)d_in[9];
    const float* wo = (const float*)d_in[10];
    const float* bo = (const float*)d_in[11];

    float *pq, *pk, *pv, *pa;
    cudaGetSymbolAddress((void**)&pq, g_q);
    cudaGetSymbolAddress((void**)&pk, g_k);
    cudaGetSymbolAddress((void**)&pv, g_v);
    cudaGetSymbolAddress((void**)&pa, g_attn);

    cudaFuncSetAttribute(proj_gemm,
                         cudaFuncAttributeMaxDynamicSharedMemorySize,
                         PROJ_SMEM_BYTES);
    cudaFuncSetAttribute(attn_kernel,
                         cudaFuncAttributeMaxDynamicSharedMemorySize,
                         ATTN_SMEM_BYTES);

    proj_gemm<<<dim3(8, 32, 3), 256, PROJ_SMEM_BYTES>>>(
        q, wq, bq, pq,
        k, wk, bk, pk,
        v, wv, bv, pv, 1);

    attn_kernel<<<dim3(16, 32), 256, ATTN_SMEM_BYTES>>>();

    proj_gemm<<<dim3(8, 32, 1), 256, PROJ_SMEM_BYTES>>>(
        pa, wo, bo, (float*)d_out,
        nullptr, nullptr, nullptr, nullptr,
        nullptr, nullptr, nullptr, nullptr, 0);
}